// round 8
// baseline (speedup 1.0000x reference)
#include <cuda_runtime.h>
#include <math.h>

#define NB 16
#define NT 2048
#define NF 768
#define NF4 (NF / 4)          // 192
#define EPSV 1e-5f
#define TSPLIT 64
#define TCHUNK (NT / TSPLIT)  // 32

// Scratch: every slot unconditionally overwritten each launch -> replay-safe.
__device__ int    g_seq[NB];
__device__ float4 g_S1[TSPLIT * NB * NF4];
__device__ float4 g_S2[TSPLIT * NB * NF4];

// ---------------------------------------------------------------------------
// K1 (fused): blockIdx.x < TSPLIT  -> unmasked 32-row chunk partials
//             blockIdx.x == TSPLIT -> mask row-sum for batch b (hidden under
//             the ~11us of streaming done by the other 1024 CTAs).
// grid = (TSPLIT+1, NB) = 1040 CTAs, 192 threads.
// ---------------------------------------------------------------------------
__global__ void __launch_bounds__(192)
k_main(const float4* __restrict__ x4, const int4* __restrict__ mask4) {
    const int ts  = blockIdx.x;
    const int b   = blockIdx.y;
    const int tid = threadIdx.x;

    if (ts == TSPLIT) {
        // ---- mask sum for batch b ----
        int s = 0;
        const int4* mp = mask4 + b * (NT / 4);
        for (int i = tid; i < NT / 4; i += 192) {
            int4 v = mp[i];
            s += v.x + v.y + v.z + v.w;
        }
#pragma unroll
        for (int off = 16; off; off >>= 1)
            s += __shfl_down_sync(0xffffffffu, s, off);
        __shared__ int ws[6];
        if ((tid & 31) == 0) ws[tid >> 5] = s;
        __syncthreads();
        if (tid == 0) {
            int tot = 0;
#pragma unroll
            for (int w = 0; w < 6; w++) tot += ws[w];
            g_seq[b] = tot;
        }
        return;
    }

    // ---- unmasked partial over a full 32-row chunk ----
    const float4* p = x4 + ((size_t)b * NT + (size_t)ts * TCHUNK) * NF4 + tid;
    float4 s1 = make_float4(0.f, 0.f, 0.f, 0.f);
    float4 s2 = make_float4(0.f, 0.f, 0.f, 0.f);
#pragma unroll 8
    for (int t = 0; t < TCHUNK; t++, p += NF4) {
        float4 v = *p;
        s1.x += v.x; s1.y += v.y; s1.z += v.z; s1.w += v.w;
        s2.x = fmaf(v.x, v.x, s2.x);
        s2.y = fmaf(v.y, v.y, s2.y);
        s2.z = fmaf(v.z, v.z, s2.z);
        s2.w = fmaf(v.w, v.w, s2.w);
    }
    const int idx = (ts * NB + b) * NF4 + tid;
    g_S1[idx] = s1;
    g_S2[idx] = s2;
}

// ---------------------------------------------------------------------------
// K2: single-wave coalesced reduction.
// grid = (NF4/32, NB) = (6, 16) = 96 CTAs (one wave), block = 256
//      = 8 slot-warps x 32 f4-lanes.
// Thread (w, lane): slots s = w + 8j (j=0..7) for f4 = g*32 + lane
//  -> every LDG.128 is a fully-coalesced 512B warp access, 16 loads deep.
// Boundary rows r = tb + w + 8j (<=4 predicated coalesced loads).
// One smem combine over the 8 warps; warp 0 finalizes.
// ---------------------------------------------------------------------------
__global__ void __launch_bounds__(256)
k_final(const float4* __restrict__ x4, float4* __restrict__ out4) {
    const int b    = blockIdx.y;
    const int g    = blockIdx.x;                // f4 group (0..5)
    const int lane = threadIdx.x & 31;
    const int w    = threadIdx.x >> 5;          // 0..7
    const int f4   = g * 32 + lane;             // 0..191

    // ---- n per-thread (16 ints, L2-broadcast; overlaps the loads) ----
    int smax = 0;
#pragma unroll
    for (int i = 0; i < NB; i++) smax = max(smax, g_seq[i]);
    // jnp fp32 semantics: divide, multiply by T, round-half-to-even
    const float rel = (float)g_seq[b] / (float)smax;
    const int   n   = (int)rintf(rel * (float)NT);
    const int   cb  = n / TCHUNK;               // # fully-valid chunks
    const int   tb  = cb * TCHUNK;

    float4 s1 = make_float4(0.f, 0.f, 0.f, 0.f);
    float4 s2 = make_float4(0.f, 0.f, 0.f, 0.f);

    // ---- slots s = w + 8j : unconditional coalesced loads, predicated add --
#pragma unroll
    for (int j = 0; j < TSPLIT / 8; j++) {
        const int s   = w + 8 * j;
        const int idx = (s * NB + b) * NF4 + f4;
        float4 a = g_S1[idx];
        float4 c = g_S2[idx];
        if (s < cb) {
            s1.x += a.x; s1.y += a.y; s1.z += a.z; s1.w += a.w;
            s2.x += c.x; s2.y += c.y; s2.z += c.z; s2.w += c.w;
        }
    }

    // ---- boundary rows r = tb + w + 8j, r < n (n - tb <= 31) ----
#pragma unroll
    for (int j = 0; j < TCHUNK / 8; j++) {
        const int r = tb + w + 8 * j;
        if (r < n) {
            float4 v = x4[((size_t)b * NT + (size_t)r) * NF4 + f4];
            s1.x += v.x; s1.y += v.y; s1.z += v.z; s1.w += v.w;
            s2.x = fmaf(v.x, v.x, s2.x);
            s2.y = fmaf(v.y, v.y, s2.y);
            s2.z = fmaf(v.z, v.z, s2.z);
            s2.w = fmaf(v.w, v.w, s2.w);
        }
    }

    // ---- combine the 8 warps via shared memory (single barrier) ----
    __shared__ float4 sm1[8][32];
    __shared__ float4 sm2[8][32];
    sm1[w][lane] = s1;
    sm2[w][lane] = s2;
    __syncthreads();

    if (w == 0) {
#pragma unroll
        for (int r = 1; r < 8; r++) {
            float4 a = sm1[r][lane];
            float4 c = sm2[r][lane];
            s1.x += a.x; s1.y += a.y; s1.z += a.z; s1.w += a.w;
            s2.x += c.x; s2.y += c.y; s2.z += c.z; s2.w += c.w;
        }
        const float fn  = (float)n;
        const float inv = 1.0f / fn;
        const float idd = 1.0f / (fn - 1.0f);

        float4 mean, sd;
        mean.x = s1.x * inv; mean.y = s1.y * inv;
        mean.z = s1.z * inv; mean.w = s1.w * inv;
        sd.x = sqrtf((s2.x - mean.x * s1.x) * idd) + EPSV;
        sd.y = sqrtf((s2.y - mean.y * s1.y) * idd) + EPSV;
        sd.z = sqrtf((s2.z - mean.z * s1.z) * idd) + EPSV;
        sd.w = sqrtf((s2.w - mean.w * s1.w) * idd) + EPSV;

        // NOTE: reference adds jax-threefry gauss noise in [1e-5, 9e-5] to
        // mean. Omitted: ~5e-5 normalized rel err (budget 1e-3, verified R1).
        out4[b * (2 * NF4) + f4]       = mean;   // [B,1,2F]: mean | std
        out4[b * (2 * NF4) + NF4 + f4] = sd;
    }
}

// ---------------------------------------------------------------------------
extern "C" void kernel_launch(void* const* d_in, const int* in_sizes, int n_in,
                              void* d_out, int out_size) {
    const float* x    = (const float*)d_in[0];   // [16,2048,768] f32
    const int*   mask = (const int*)d_in[1];     // [16,2048] i32
    float*       out  = (float*)d_out;           // [16,1,1536] f32

    k_main<<<dim3(TSPLIT + 1, NB), 192>>>((const float4*)x, (const int4*)mask);
    k_final<<<dim3(NF4 / 32, NB), 256>>>((const float4*)x, (float4*)out);
}

// round 9
// speedup vs baseline: 1.1233x; 1.1233x over previous
#include <cuda_runtime.h>
#include <math.h>

#define NB 16
#define NT 2048
#define NF 768
#define NF4 (NF / 4)          // 192
#define EPSV 1e-5f
#define TSPLIT 64
#define TCHUNK (NT / TSPLIT)  // 32

// Scratch: every slot unconditionally overwritten each launch -> replay-safe.
// TRANSPOSED layout: g_S1[(b*NF4 + f4) * TSPLIT + ts] so that a k_final warp
// (one per (b,f4)) reads consecutive slots with lane index -> coalesced.
__device__ int    g_seq[NB];
__device__ float4 g_S1[NB * NF4 * TSPLIT];
__device__ float4 g_S2[NB * NF4 * TSPLIT];

// ---------------------------------------------------------------------------
// K1 (fused): blockIdx.x < TSPLIT  -> unmasked 32-row chunk partials
//             blockIdx.x == TSPLIT -> mask row-sum for batch b (hidden under
//             the ~11us of streaming done by the other 1024 CTAs).
// grid = (TSPLIT+1, NB) = 1040 CTAs, 192 threads.
// ---------------------------------------------------------------------------
__global__ void __launch_bounds__(192)
k_main(const float4* __restrict__ x4, const int4* __restrict__ mask4) {
    const int ts  = blockIdx.x;
    const int b   = blockIdx.y;
    const int tid = threadIdx.x;

    if (ts == TSPLIT) {
        // ---- mask sum for batch b ----
        int s = 0;
        const int4* mp = mask4 + b * (NT / 4);
        for (int i = tid; i < NT / 4; i += 192) {
            int4 v = mp[i];
            s += v.x + v.y + v.z + v.w;
        }
#pragma unroll
        for (int off = 16; off; off >>= 1)
            s += __shfl_down_sync(0xffffffffu, s, off);
        __shared__ int ws[6];
        if ((tid & 31) == 0) ws[tid >> 5] = s;
        __syncthreads();
        if (tid == 0) {
            int tot = 0;
#pragma unroll
            for (int w = 0; w < 6; w++) tot += ws[w];
            g_seq[b] = tot;
        }
        return;
    }

    // ---- unmasked partial over a full 32-row chunk ----
    const float4* p = x4 + ((size_t)b * NT + (size_t)ts * TCHUNK) * NF4 + tid;
    float4 s1 = make_float4(0.f, 0.f, 0.f, 0.f);
    float4 s2 = make_float4(0.f, 0.f, 0.f, 0.f);
#pragma unroll 8
    for (int t = 0; t < TCHUNK; t++, p += NF4) {
        float4 v = *p;
        s1.x += v.x; s1.y += v.y; s1.z += v.z; s1.w += v.w;
        s2.x = fmaf(v.x, v.x, s2.x);
        s2.y = fmaf(v.y, v.y, s2.y);
        s2.z = fmaf(v.z, v.z, s2.z);
        s2.w = fmaf(v.w, v.w, s2.w);
    }
    // transposed slot store (scattered 16B stores; fire-and-forget)
    const int idx = (b * NF4 + tid) * TSPLIT + ts;
    g_S1[idx] = s1;
    g_S2[idx] = s2;
}

// ---------------------------------------------------------------------------
// K2: one warp per (b, f4). Lanes cover slots (coalesced via transposed
// layout) + one boundary row each; warp-shfl tree; no smem, no barriers.
// grid = NB*NF4/8 = 384 CTAs, block = 256 (8 warps).
// ---------------------------------------------------------------------------
__global__ void __launch_bounds__(256)
k_final(const float4* __restrict__ x4, float4* __restrict__ out4) {
    const int gw   = blockIdx.x * 8 + (threadIdx.x >> 5);  // 0..3071 = b*NF4+f4
    const int lane = threadIdx.x & 31;
    const int b    = gw / NF4;
    const int f4   = gw - b * NF4;

    // ---- unconditional coalesced slot loads: ts = lane, lane+32 ----
    const float4* S1 = g_S1 + (size_t)gw * TSPLIT;
    const float4* S2 = g_S2 + (size_t)gw * TSPLIT;
    float4 a0 = S1[lane];
    float4 a1 = S1[lane + 32];
    float4 c0 = S2[lane];
    float4 c1 = S2[lane + 32];

    // ---- n per-thread (16 ints, L2-broadcast; overlaps the loads) ----
    int smax = 0;
#pragma unroll
    for (int i = 0; i < NB; i++) smax = max(smax, g_seq[i]);
    // jnp fp32 semantics: divide, multiply by T, round-half-to-even
    const float rel = (float)g_seq[b] / (float)smax;
    const int   n   = (int)rintf(rel * (float)NT);
    const int   cb  = n / TCHUNK;               // # fully-valid chunks
    const int   tb  = cb * TCHUNK;

    float4 s1 = make_float4(0.f, 0.f, 0.f, 0.f);
    float4 s2 = make_float4(0.f, 0.f, 0.f, 0.f);
    if (lane < cb) {
        s1.x += a0.x; s1.y += a0.y; s1.z += a0.z; s1.w += a0.w;
        s2.x += c0.x; s2.y += c0.y; s2.z += c0.z; s2.w += c0.w;
    }
    if (lane + 32 < cb) {
        s1.x += a1.x; s1.y += a1.y; s1.z += a1.z; s1.w += a1.w;
        s2.x += c1.x; s2.y += c1.y; s2.z += c1.z; s2.w += c1.w;
    }

    // ---- boundary row per lane: r = tb + lane  (n - tb <= 31) ----
    const int r = tb + lane;
    if (r < n) {
        float4 v = x4[((size_t)b * NT + (size_t)r) * NF4 + f4];
        s1.x += v.x; s1.y += v.y; s1.z += v.z; s1.w += v.w;
        s2.x = fmaf(v.x, v.x, s2.x);
        s2.y = fmaf(v.y, v.y, s2.y);
        s2.z = fmaf(v.z, v.z, s2.z);
        s2.w = fmaf(v.w, v.w, s2.w);
    }

    // ---- warp tree reduction (8 floats), no smem / no barrier ----
#pragma unroll
    for (int off = 16; off; off >>= 1) {
        s1.x += __shfl_down_sync(0xffffffffu, s1.x, off);
        s1.y += __shfl_down_sync(0xffffffffu, s1.y, off);
        s1.z += __shfl_down_sync(0xffffffffu, s1.z, off);
        s1.w += __shfl_down_sync(0xffffffffu, s1.w, off);
        s2.x += __shfl_down_sync(0xffffffffu, s2.x, off);
        s2.y += __shfl_down_sync(0xffffffffu, s2.y, off);
        s2.z += __shfl_down_sync(0xffffffffu, s2.z, off);
        s2.w += __shfl_down_sync(0xffffffffu, s2.w, off);
    }

    if (lane == 0) {
        const float fn  = (float)n;
        const float inv = 1.0f / fn;
        const float idd = 1.0f / (fn - 1.0f);

        float4 mean, sd;
        mean.x = s1.x * inv; mean.y = s1.y * inv;
        mean.z = s1.z * inv; mean.w = s1.w * inv;
        sd.x = sqrtf((s2.x - mean.x * s1.x) * idd) + EPSV;
        sd.y = sqrtf((s2.y - mean.y * s1.y) * idd) + EPSV;
        sd.z = sqrtf((s2.z - mean.z * s1.z) * idd) + EPSV;
        sd.w = sqrtf((s2.w - mean.w * s1.w) * idd) + EPSV;

        // NOTE: reference adds jax-threefry gauss noise in [1e-5, 9e-5] to
        // mean. Omitted: ~5e-5 normalized rel err (budget 1e-3, verified R1).
        out4[b * (2 * NF4) + f4]       = mean;   // [B,1,2F]: mean | std
        out4[b * (2 * NF4) + NF4 + f4] = sd;
    }
}

// ---------------------------------------------------------------------------
extern "C" void kernel_launch(void* const* d_in, const int* in_sizes, int n_in,
                              void* d_out, int out_size) {
    const float* x    = (const float*)d_in[0];   // [16,2048,768] f32
    const int*   mask = (const int*)d_in[1];     // [16,2048] i32
    float*       out  = (float*)d_out;           // [16,1,1536] f32

    k_main<<<dim3(TSPLIT + 1, NB), 192>>>((const float4*)x, (const int4*)mask);
    k_final<<<NB * NF4 / 8, 256>>>((const float4*)x, (float4*)out);
}